// round 8
// baseline (speedup 1.0000x reference)
#include <cuda_runtime.h>

#define TT      65536
#define HID     128
#define G3      384
#define INS     96
#define LIN     32
#define CHUNK   8
#define NCHUNK  (TT / CHUNK)   // 8192
#define NPROD   147
#define NBLK    (NPROD + 1)    // 148
#define NT      512

#define IG_CHUNK_BYTES (CHUNK * G3 * 4)          // 12288
#define XL_CHUNK_BYTES (CHUNK * LIN * 4)         // 1024
#define TX_BYTES       (IG_CHUNK_BYTES + XL_CHUNK_BYTES)

// 96 MB scratch for precomputed input gates, + chunk-ready flags
__device__ float g_ig[TT * G3];
__device__ int   g_flag[NCHUNK];

// ---------- f32x2 helpers ----------
static __device__ __forceinline__ unsigned long long pk2(float a, float b) {
    unsigned long long r;
    asm("mov.b64 %0, {%1,%2};" : "=l"(r) : "f"(a), "f"(b));
    return r;
}
static __device__ __forceinline__ void fma2(unsigned long long& d,
                                            unsigned long long a,
                                            unsigned long long b) {
    asm("fma.rn.f32x2 %0, %1, %2, %0;" : "+l"(d) : "l"(a), "l"(b));
}
static __device__ __forceinline__ float lo_hi_sum(unsigned long long v) {
    float lo, hi;
    asm("mov.b64 {%0,%1}, %2;" : "=f"(lo), "=f"(hi) : "l"(v));
    return lo + hi;
}

// ---------- fast transcendentals (MUFU-based, ~1e-6 rel err) ----------
static __device__ __forceinline__ float fex2(float x) {
    float r; asm("ex2.approx.f32 %0, %1;" : "=f"(r) : "f"(x)); return r;
}
static __device__ __forceinline__ float frcp(float x) {
    float r; asm("rcp.approx.f32 %0, %1;" : "=f"(r) : "f"(x)); return r;
}
static __device__ __forceinline__ float sigmoid_f(float x) {
    return frcp(1.0f + fex2(-1.4426950408889634f * x));
}
static __device__ __forceinline__ float tanh_f(float x) {
    float ax = fabsf(x);
    float e  = fex2(-2.885390081777927f * ax);   // exp(-2*ax) via ex2
    float t  = (1.0f - e) * frcp(1.0f + e);
    return copysignf(t, x);
}

// ---------- sync / async primitives ----------
static __device__ __forceinline__ void wait_flag(const int* fp) {
    int f;
    do { asm volatile("ld.acquire.gpu.global.b32 %0, [%1];" : "=r"(f) : "l"(fp)); } while (f == 0);
}
static __device__ __forceinline__ int ld_relaxed(const int* fp) {
    int f;
    asm volatile("ld.relaxed.gpu.global.b32 %0, [%1];" : "=r"(f) : "l"(fp));
    return f;
}
static __device__ __forceinline__ unsigned smem_u32(const void* p) {
    unsigned a;
    asm("{ .reg .u64 t; cvta.to.shared.u64 t, %1; cvt.u32.u64 %0, t; }" : "=r"(a) : "l"(p));
    return a;
}
static __device__ __forceinline__ void mbar_init(unsigned mbar, unsigned cnt) {
    asm volatile("mbarrier.init.shared.b64 [%0], %1;" :: "r"(mbar), "r"(cnt) : "memory");
}
static __device__ __forceinline__ void mbar_expect_tx(unsigned mbar, unsigned bytes) {
    asm volatile("mbarrier.arrive.expect_tx.shared.b64 _, [%0], %1;" :: "r"(mbar), "r"(bytes) : "memory");
}
static __device__ __forceinline__ void mbar_wait(unsigned mbar, unsigned parity) {
    asm volatile(
        "{\n\t.reg .pred P;\n\t"
        "W%=:\n\t"
        "mbarrier.try_wait.parity.shared::cta.b64 P, [%0], %1;\n\t"
        "@!P bra W%=;\n\t}"
        :: "r"(mbar), "r"(parity) : "memory");
}
static __device__ __forceinline__ void bulk_g2s(unsigned dst, const void* src,
                                                unsigned bytes, unsigned mbar) {
    asm volatile(
        "cp.async.bulk.shared::cta.global.mbarrier::complete_tx::bytes [%0], [%1], %2, [%3];"
        :: "r"(dst), "l"(src), "r"(bytes), "r"(mbar) : "memory");
}

// ---------- clear flags each launch (graph-replay safe) ----------
__global__ void gru_clear_flags() {
    int i = blockIdx.x * blockDim.x + threadIdx.x;
    if (i < NCHUNK) g_flag[i] = 0;
}

// shared memory carve (floats):
//  [0 .. 6144)       igates double buffer: 2 chunks x CHUNK x 384
//  [6144 .. 6656)    x_lin double buffer:  2 chunks x CHUNK x 32
//  [6656 .. 6800)    shA (padded h, 144)
//  [6800 .. 6944)    shB (padded h, 144)
//  producer branch reuses [0 .. 864) for x staging

__global__ __launch_bounds__(NT, 1)
void gru_fused(const float* __restrict__ x_gru,   // (T, 96)
               const float* __restrict__ x_lin,   // (T, 32)
               const float* __restrict__ h_init,  // (128,)
               const float* __restrict__ w_ih,    // (384, 96)
               const float* __restrict__ w_hh,    // (384, 128)
               const float* __restrict__ b_ih,    // (384,)
               const float* __restrict__ b_nv,    // (128,)
               const float* __restrict__ lbias_p, // (1,)
               float* __restrict__ out)           // (T, 1)
{
    __shared__ __align__(16) float sm[6944];
    __shared__ __align__(8) unsigned long long mbar_storage;
    const int tid = threadIdx.x;

    if (blockIdx.x != 0) {
        // ============ PRODUCER: igates = x_gru @ w_ih.T + b_ih, chunks of 8 ============
        const int b = blockIdx.x - 1;   // 0..146
        float wreg[INS];
        float bih = 0.0f;
        if (tid < G3) {
            const float* wp = w_ih + tid * INS;
            #pragma unroll
            for (int k = 0; k < INS; k++) wreg[k] = wp[k];
            bih = b_ih[tid];
        }
        for (int c = b; c < NCHUNK; c += NPROD) {
            const int t0 = c * CHUNK;
            __syncthreads();  // smem reuse guard across chunks
            for (int i = tid; i < CHUNK * INS; i += NT) {
                int ttl = i / INS, k = i % INS;
                sm[k * 9 + ttl] = x_gru[(size_t)(t0 + ttl) * INS + k];
            }
            __syncthreads();
            if (tid < G3) {
                float acc[CHUNK];
                #pragma unroll
                for (int ttl = 0; ttl < CHUNK; ttl++) acc[ttl] = bih;
                #pragma unroll 8
                for (int k = 0; k < INS; k++) {
                    const float w = wreg[k];
                    #pragma unroll
                    for (int ttl = 0; ttl < CHUNK; ttl++)
                        acc[ttl] = fmaf(w, sm[k * 9 + ttl], acc[ttl]);
                }
                #pragma unroll
                for (int ttl = 0; ttl < CHUNK; ttl++)
                    g_ig[(size_t)(t0 + ttl) * G3 + tid] = acc[ttl];
            }
            __syncthreads();  // all stores issued before the release
            if (tid == 0) {
                __threadfence();
                atomicExch(&g_flag[c], 1);
            }
        }
        return;
    }

    // ===================== SCAN (single persistent CTA, 512 threads) =====================
    // warp w, lane l: row = w*8 + l/4 (0..127), kq = l&3 selects a 32-wide K slice.
    const int wid  = tid >> 5;
    const int lane = tid & 31;
    const int row  = wid * 8 + (lane >> 2);
    const int kq   = lane & 3;

    float* igb = sm;            // [2][CHUNK*G3]
    float* xlb = sm + 6144;     // [2][CHUNK*LIN]
    float* shA = sm + 6656;     // padded h: element e at word (e>>5)*36 + (e&31)
    float* shB = sm + 6800;
    const unsigned mbar = smem_u32(&mbar_storage);

    // weights: 3 gates x 32 K-values = 48 f32x2 regs
    unsigned long long wr_[16], wz_[16], wn_[16];
    {
        const float2* p0 = (const float2*)(w_hh + (size_t)(row      ) * HID) + kq * 16;
        const float2* p1 = (const float2*)(w_hh + (size_t)(row + 128) * HID) + kq * 16;
        const float2* p2 = (const float2*)(w_hh + (size_t)(row + 256) * HID) + kq * 16;
        #pragma unroll
        for (int j = 0; j < 16; j++) { float2 v = p0[j]; wr_[j] = pk2(v.x, v.y); }
        #pragma unroll
        for (int j = 0; j < 16; j++) { float2 v = p1[j]; wz_[j] = pk2(v.x, v.y); }
        #pragma unroll
        for (int j = 0; j < 16; j++) { float2 v = p2[j]; wn_[j] = pk2(v.x, v.y); }
    }
    const float bn    = b_nv[row];
    const float lbias = lbias_p[0];
    float h_reg = h_init[row];
    if (kq == 0) shA[(row >> 5) * 36 + (row & 31)] = h_reg;
    float xl_reg = 0.0f;   // x_lin[t-1] for the deferred output (warp 0 lanes)

    // prologue: init mbar, kick copy of chunk 0
    if (tid == 0) {
        mbar_init(mbar, 1);
        wait_flag(&g_flag[0]);
        mbar_expect_tx(mbar, TX_BYTES);
        bulk_g2s(smem_u32(igb), g_ig, IG_CHUNK_BYTES, mbar);
        bulk_g2s(smem_u32(xlb), x_lin, XL_CHUNK_BYTES, mbar);
    }
    int flag_pre = 0;   // relaxed pre-read of flag[c+1], one chunk ahead (tid 0 only)

    auto step = [&](int t, int s, const float* hrd, float* hwr,
                    const float* ig, const float* xl) {
        // igates from smem (broadcast LDS, hidden under FMA phase)
        const float igr = ig[s * G3 + row];
        const float igz = ig[s * G3 + 128 + row];
        const float ign = ig[s * G3 + 256 + row];

        // deferred output for t-1 (warp 0): h(t-1) is hrd, overlaps matvec issue
        if (wid == 0) {
            if (t > 0) {
                float p = hrd[lane] * xl_reg;
                p += __shfl_xor_sync(0xffffffffu, p, 1);
                p += __shfl_xor_sync(0xffffffffu, p, 2);
                p += __shfl_xor_sync(0xffffffffu, p, 4);
                p += __shfl_xor_sync(0xffffffffu, p, 8);
                p += __shfl_xor_sync(0xffffffffu, p, 16);
                if (lane == 0) out[t - 1] = p + lbias;
            }
            xl_reg = xl[s * LIN + lane];   // x_lin[t], for the next step's output
        }

        // ---- matvec: 3 gate slices over this thread's 32 h values ----
        unsigned long long ar = 0ull, az = 0ull, an2 = 0ull;
        const ulonglong2* h2 = (const ulonglong2*)(hrd + kq * 36);
        #pragma unroll
        for (int j = 0; j < 8; j++) {
            ulonglong2 v = h2[j];
            fma2(ar,  wr_[2 * j], v.x); fma2(ar,  wr_[2 * j + 1], v.y);
            fma2(az,  wz_[2 * j], v.x); fma2(az,  wz_[2 * j + 1], v.y);
            fma2(an2, wn_[2 * j], v.x); fma2(an2, wn_[2 * j + 1], v.y);
        }
        float gr = lo_hi_sum(ar), gz = lo_hi_sum(az), gn = lo_hi_sum(an2);
        gr += __shfl_xor_sync(0xffffffffu, gr, 1);
        gr += __shfl_xor_sync(0xffffffffu, gr, 2);
        gz += __shfl_xor_sync(0xffffffffu, gz, 1);
        gz += __shfl_xor_sync(0xffffffffu, gz, 2);
        gn += __shfl_xor_sync(0xffffffffu, gn, 1);
        gn += __shfl_xor_sync(0xffffffffu, gn, 2);

        const float r    = sigmoid_f(gr + igr);
        const float z    = sigmoid_f(gz + igz);
        const float n    = tanh_f(ign + r * (gn + bn));
        const float hnew = fmaf(z, h_reg - n, n);
        h_reg = hnew;
        if (kq == 0) hwr[(row >> 5) * 36 + (row & 31)] = hnew;
        __syncthreads();  // single barrier per step (h + xl/ig buffers protected)
    };

    for (int c = 0; c < NCHUNK; c++) {
        const float* ig = igb + (c & 1) * (CHUNK * G3);
        const float* xl = xlb + (c & 1) * (CHUNK * LIN);

        if (tid == 0) mbar_wait(mbar, (unsigned)(c & 1));  // chunk c copy complete
        __syncthreads();                                   // publish buffer to all

        if (tid == 0 && c + 1 < NCHUNK) {
            // flag for c+1: usually pre-confirmed last chunk; else poll
            if (flag_pre) asm volatile("fence.acq_rel.gpu;" ::: "memory");
            else          wait_flag(&g_flag[c + 1]);
            mbar_expect_tx(mbar, TX_BYTES);
            bulk_g2s(smem_u32(igb + ((c + 1) & 1) * (CHUNK * G3)),
                     g_ig + (size_t)(c + 1) * (CHUNK * G3), IG_CHUNK_BYTES, mbar);
            bulk_g2s(smem_u32(xlb + ((c + 1) & 1) * (CHUNK * LIN)),
                     x_lin + (size_t)(c + 1) * (CHUNK * LIN), XL_CHUNK_BYTES, mbar);
            // pre-read flag for c+2 (latency hidden across the chunk)
            flag_pre = (c + 2 < NCHUNK) ? ld_relaxed(&g_flag[c + 2]) : 1;
        }

        const int t0 = c * CHUNK;
        #pragma unroll 1
        for (int s = 0; s < CHUNK; s += 2) {
            step(t0 + s,     s,     shA, shB, ig, xl);
            step(t0 + s + 1, s + 1, shB, shA, ig, xl);
        }
    }

    // final output: h(TT-1) lives in shA (odd last step writes A); xl_reg = x_lin[TT-1]
    if (wid == 0) {
        float p = shA[lane] * xl_reg;
        p += __shfl_xor_sync(0xffffffffu, p, 1);
        p += __shfl_xor_sync(0xffffffffu, p, 2);
        p += __shfl_xor_sync(0xffffffffu, p, 4);
        p += __shfl_xor_sync(0xffffffffu, p, 8);
        p += __shfl_xor_sync(0xffffffffu, p, 16);
        if (lane == 0) out[TT - 1] = p + lbias;
    }
}

extern "C" void kernel_launch(void* const* d_in, const int* in_sizes, int n_in,
                              void* d_out, int out_size) {
    const float* x_gru = (const float*)d_in[0];  // (65536, 96)
    const float* x_lin = (const float*)d_in[1];  // (65536, 32)
    const float* h0    = (const float*)d_in[2];  // (128,)
    const float* w_ih  = (const float*)d_in[3];  // (384, 96)
    const float* w_hh  = (const float*)d_in[4];  // (384, 128)
    const float* b_ih  = (const float*)d_in[5];  // (384,)
    const float* b_n   = (const float*)d_in[6];  // (128,)
    const float* lb    = (const float*)d_in[7];  // (1,)
    float* out = (float*)d_out;                  // (65536, 1)

    gru_clear_flags<<<(NCHUNK + 255) / 256, 256>>>();
    gru_fused<<<NBLK, NT>>>(x_gru, x_lin, h0, w_ih, w_hh, b_ih, b_n, lb, out);
}

// round 13
// speedup vs baseline: 1.2155x; 1.2155x over previous
#include <cuda_runtime.h>

#define TT      65536
#define HID     128
#define G3      384
#define INS     96
#define LIN     32
#define CHUNK   8
#define NCHUNK  (TT / CHUNK)   // 8192
#define NPROD   147
#define NBLK    (NPROD + 1)    // 148
#define NT      1024

#define IG_CHUNK_F  (CHUNK * G3)                 // 3072 floats
#define XL_CHUNK_F  (CHUNK * LIN)                // 256 floats
#define IG_CHUNK_BYTES (IG_CHUNK_F * 4)          // 12288
#define XL_CHUNK_BYTES (XL_CHUNK_F * 4)          // 1024
#define TX_BYTES       (IG_CHUNK_BYTES + XL_CHUNK_BYTES)

// 96 MB scratch for precomputed input gates, + chunk-ready flags
__device__ float g_ig[TT * G3];
__device__ int   g_flag[NCHUNK];

// ---------- f32x2 helpers ----------
static __device__ __forceinline__ unsigned long long pk2(float a, float b) {
    unsigned long long r;
    asm("mov.b64 %0, {%1,%2};" : "=l"(r) : "f"(a), "f"(b));
    return r;
}
static __device__ __forceinline__ void fma2(unsigned long long& d,
                                            unsigned long long a,
                                            unsigned long long b) {
    asm("fma.rn.f32x2 %0, %1, %2, %0;" : "+l"(d) : "l"(a), "l"(b));
}
static __device__ __forceinline__ float lo_hi_sum(unsigned long long v) {
    float lo, hi;
    asm("mov.b64 {%0,%1}, %2;" : "=f"(lo), "=f"(hi) : "l"(v));
    return lo + hi;
}

// ---------- single-MUFU nonlinearities ----------
static __device__ __forceinline__ float tanh_fast(float x) {
    float r; asm("tanh.approx.f32 %0, %1;" : "=f"(r) : "f"(x)); return r;
}
static __device__ __forceinline__ float sigmoid_f(float x) {
    // sigma(x) = 0.5*tanh(x/2) + 0.5   (1 MUFU + 2 FMA)
    return fmaf(0.5f, tanh_fast(0.5f * x), 0.5f);
}

// ---------- sync / async primitives ----------
static __device__ __forceinline__ void wait_flag(const int* fp) {
    int f;
    do { asm volatile("ld.acquire.gpu.global.b32 %0, [%1];" : "=r"(f) : "l"(fp)); } while (f == 0);
}
static __device__ __forceinline__ int ld_relaxed(const int* fp) {
    int f;
    asm volatile("ld.relaxed.gpu.global.b32 %0, [%1];" : "=r"(f) : "l"(fp));
    return f;
}
static __device__ __forceinline__ unsigned smem_u32(const void* p) {
    unsigned a;
    asm("{ .reg .u64 t; cvta.to.shared.u64 t, %1; cvt.u32.u64 %0, t; }" : "=r"(a) : "l"(p));
    return a;
}
static __device__ __forceinline__ void mbar_init(unsigned mbar, unsigned cnt) {
    asm volatile("mbarrier.init.shared.b64 [%0], %1;" :: "r"(mbar), "r"(cnt) : "memory");
}
static __device__ __forceinline__ void mbar_expect_tx(unsigned mbar, unsigned bytes) {
    asm volatile("mbarrier.arrive.expect_tx.shared.b64 _, [%0], %1;" :: "r"(mbar), "r"(bytes) : "memory");
}
static __device__ __forceinline__ void mbar_wait(unsigned mbar, unsigned parity) {
    asm volatile(
        "{\n\t.reg .pred P;\n\t"
        "W%=:\n\t"
        "mbarrier.try_wait.parity.shared::cta.b64 P, [%0], %1;\n\t"
        "@!P bra W%=;\n\t}"
        :: "r"(mbar), "r"(parity) : "memory");
}
static __device__ __forceinline__ void bulk_g2s(unsigned dst, const void* src,
                                                unsigned bytes, unsigned mbar) {
    asm volatile(
        "cp.async.bulk.shared::cta.global.mbarrier::complete_tx::bytes [%0], [%1], %2, [%3];"
        :: "r"(dst), "l"(src), "r"(bytes), "r"(mbar) : "memory");
}

// ---------- clear flags each launch (graph-replay safe) ----------
__global__ void gru_clear_flags() {
    int i = blockIdx.x * blockDim.x + threadIdx.x;
    if (i < NCHUNK) g_flag[i] = 0;
}

// shared float carve (scan block):
//  [0 .. 6144)      igates double buffer: 2 x 8 x 384
//  [6144 .. 6656)   x_lin  double buffer: 2 x 8 x 32
//  [6656 .. 6816)   shA (padded h: element e at (e>>4)*20 + (e&15); 160 words)
//  [6816 .. 6976)   shB
//  [6976 .. 6984)   soA (8 output partials, even steps)
//  [6984 .. 6992)   soB (odd steps)
//  producer branch reuses [0 .. 864) for x staging

__global__ __launch_bounds__(NT, 1)
void gru_fused(const float* __restrict__ x_gru,   // (T, 96)
               const float* __restrict__ x_lin,   // (T, 32)
               const float* __restrict__ h_init,  // (128,)
               const float* __restrict__ w_ih,    // (384, 96)
               const float* __restrict__ w_hh,    // (384, 128)
               const float* __restrict__ b_ih,    // (384,)
               const float* __restrict__ b_nv,    // (128,)
               const float* __restrict__ lbias_p, // (1,)
               float* __restrict__ out)           // (T, 1)
{
    __shared__ __align__(16) float sm[6992];
    __shared__ __align__(8) unsigned long long mbar_storage;
    const int tid = threadIdx.x;

    if (blockIdx.x != 0) {
        // ======== PRODUCER: igates = x_gru @ w_ih.T + b_ih (row, k-half split) ========
        const int b      = blockIdx.x - 1;     // 0..146
        const bool act   = (tid < 2 * G3);     // 768 active
        const int  prow  = tid >> 1;           // 0..383
        const int  kh    = tid & 1;            // k-half
        float wreg[48];
        float bih = 0.0f;
        if (act) {
            const float* wp = w_ih + prow * INS + kh * 48;
            #pragma unroll
            for (int j = 0; j < 48; j++) wreg[j] = wp[j];
            if (kh == 0) bih = b_ih[prow];
        }
        for (int c = b; c < NCHUNK; c += NPROD) {
            const int t0 = c * CHUNK;
            __syncthreads();  // smem reuse guard across chunks
            for (int i = tid; i < CHUNK * INS; i += NT) {
                int ttl = i / INS, k = i % INS;
                sm[k * 9 + ttl] = x_gru[(size_t)(t0 + ttl) * INS + k];
            }
            __syncthreads();
            if (act) {
                float acc[CHUNK];
                #pragma unroll
                for (int ttl = 0; ttl < CHUNK; ttl++) acc[ttl] = bih;
                #pragma unroll 8
                for (int j = 0; j < 48; j++) {
                    const float w = wreg[j];
                    const float* xs = &sm[(kh * 48 + j) * 9];
                    #pragma unroll
                    for (int ttl = 0; ttl < CHUNK; ttl++)
                        acc[ttl] = fmaf(w, xs[ttl], acc[ttl]);
                }
                #pragma unroll
                for (int ttl = 0; ttl < CHUNK; ttl++)
                    acc[ttl] += __shfl_xor_sync(0xffffffffu, acc[ttl], 1);
                if (kh == 0) {
                    #pragma unroll
                    for (int ttl = 0; ttl < CHUNK; ttl++)
                        g_ig[(size_t)(t0 + ttl) * G3 + prow] = acc[ttl];
                }
            }
            __syncthreads();  // all stores issued before the release
            if (tid == 0) {
                __threadfence();
                atomicExch(&g_flag[c], 1);
            }
        }
        return;
    }

    // ============ SCAN: 1024 threads, row = wid*4 + lane/8, kq = lane&7 ============
    const int wid  = tid >> 5;            // 0..31
    const int lane = tid & 31;
    const int row  = wid * 4 + (lane >> 3);  // 0..127
    const int kq   = lane & 7;               // 16-wide K slice

    float* igb = sm;            // [2][3072]
    float* xlb = sm + 6144;     // [2][256]
    float* shA = sm + 6656;     // padded h (160)
    float* shB = sm + 6816;
    float* soA = sm + 6976;     // 8 partials
    float* soB = sm + 6984;
    const unsigned mbar = smem_u32(&mbar_storage);

    // weights: 3 gates x 16 K = 8 f32x2 each
    unsigned long long wr_[8], wz_[8], wn_[8];
    {
        const float2* p0 = (const float2*)(w_hh + (size_t)(row      ) * HID) + kq * 8;
        const float2* p1 = (const float2*)(w_hh + (size_t)(row + 128) * HID) + kq * 8;
        const float2* p2 = (const float2*)(w_hh + (size_t)(row + 256) * HID) + kq * 8;
        #pragma unroll
        for (int j = 0; j < 8; j++) { float2 v = p0[j]; wr_[j] = pk2(v.x, v.y); }
        #pragma unroll
        for (int j = 0; j < 8; j++) { float2 v = p1[j]; wz_[j] = pk2(v.x, v.y); }
        #pragma unroll
        for (int j = 0; j < 8; j++) { float2 v = p2[j]; wn_[j] = pk2(v.x, v.y); }
    }
    const float bn    = b_nv[row];
    const float lbias = lbias_p[0];
    float h_reg = h_init[row];
    if (kq == 0) shA[((row >> 4) * 20) + (row & 15)] = h_reg;

    // prologue: init mbar, kick copy of chunk 0
    if (tid == 0) {
        mbar_init(mbar, 1);
        wait_flag(&g_flag[0]);
        mbar_expect_tx(mbar, TX_BYTES);
        bulk_g2s(smem_u32(igb), g_ig, IG_CHUNK_BYTES, mbar);
        bulk_g2s(smem_u32(xlb), x_lin, XL_CHUNK_BYTES, mbar);
    }
    int flag_pre = 0;

    auto step = [&](int t, int s, const float* hrd, float* hwr,
                    float* so_w, const float* so_r,
                    const float* ig, const float* xl) {
        // finalize previous step's output (warp 8 lane 0 — off the rows-0..31 path tail)
        if (tid == 256 && t > 0) {
            float4 a = *(const float4*)so_r;
            float4 b4 = *(const float4*)(so_r + 4);
            out[t - 1] = a.x + a.y + a.z + a.w + b4.x + b4.y + b4.z + b4.w + lbias;
        }

        // igates + x_lin from smem (broadcast LDS)
        const float igr = ig[s * G3 + row];
        const float igz = ig[s * G3 + 128 + row];
        const float ign = ig[s * G3 + 256 + row];
        float xlv = 0.0f;
        if (wid < 8) xlv = xl[s * LIN + row];   // rows 0..31 only

        // ---- matvec: 3 gates over this thread's 16 h values ----
        unsigned long long ar = 0ull, az = 0ull, an2 = 0ull;
        const ulonglong2* h2 = (const ulonglong2*)(hrd + kq * 20);
        #pragma unroll
        for (int j = 0; j < 4; j++) {
            ulonglong2 v = h2[j];
            fma2(ar,  wr_[2 * j], v.x); fma2(ar,  wr_[2 * j + 1], v.y);
            fma2(az,  wz_[2 * j], v.x); fma2(az,  wz_[2 * j + 1], v.y);
            fma2(an2, wn_[2 * j], v.x); fma2(an2, wn_[2 * j + 1], v.y);
        }
        float gr = lo_hi_sum(ar), gz = lo_hi_sum(az), gn = lo_hi_sum(an2);
        gr += __shfl_xor_sync(0xffffffffu, gr, 1);
        gr += __shfl_xor_sync(0xffffffffu, gr, 2);
        gr += __shfl_xor_sync(0xffffffffu, gr, 4);
        gz += __shfl_xor_sync(0xffffffffu, gz, 1);
        gz += __shfl_xor_sync(0xffffffffu, gz, 2);
        gz += __shfl_xor_sync(0xffffffffu, gz, 4);
        gn += __shfl_xor_sync(0xffffffffu, gn, 1);
        gn += __shfl_xor_sync(0xffffffffu, gn, 2);
        gn += __shfl_xor_sync(0xffffffffu, gn, 4);

        // gates (redundant on 8 kq lanes; 3 MUFU total)
        const float r    = sigmoid_f(gr + igr);
        const float z    = sigmoid_f(gz + igz);
        const float n    = tanh_fast(ign + r * (gn + bn));
        const float hnew = fmaf(z, h_reg - n, n);
        h_reg = hnew;
        if (kq == 0) hwr[((row >> 4) * 20) + (row & 15)] = hnew;

        // output partial: rows 0..31 live in warps 0..7 at lanes 0,8,16,24
        if (wid < 8) {
            float p = (kq == 0) ? hnew * xlv : 0.0f;
            p += __shfl_xor_sync(0xffffffffu, p, 8);
            p += __shfl_xor_sync(0xffffffffu, p, 16);
            if (lane == 0) so_w[wid] = p;
        }
        __syncthreads();  // single barrier per step
    };

    for (int c = 0; c < NCHUNK; c++) {
        const float* ig = igb + (c & 1) * IG_CHUNK_F;
        const float* xl = xlb + (c & 1) * XL_CHUNK_F;

        if (tid == 0) mbar_wait(mbar, (unsigned)(c & 1));  // chunk c copy complete
        __syncthreads();                                   // publish buffer

        if (tid == 0 && c + 1 < NCHUNK) {
            if (flag_pre) asm volatile("fence.acq_rel.gpu;" ::: "memory");
            else          wait_flag(&g_flag[c + 1]);
            mbar_expect_tx(mbar, TX_BYTES);
            bulk_g2s(smem_u32(igb + ((c + 1) & 1) * IG_CHUNK_F),
                     g_ig + (size_t)(c + 1) * IG_CHUNK_F, IG_CHUNK_BYTES, mbar);
            bulk_g2s(smem_u32(xlb + ((c + 1) & 1) * XL_CHUNK_F),
                     x_lin + (size_t)(c + 1) * XL_CHUNK_F, XL_CHUNK_BYTES, mbar);
            flag_pre = (c + 2 < NCHUNK) ? ld_relaxed(&g_flag[c + 2]) : 1;
        }

        const int t0 = c * CHUNK;
        #pragma unroll 1
        for (int s = 0; s < CHUNK; s += 2) {
            step(t0 + s,     s,     shA, shB, soA, soB, ig, xl);
            step(t0 + s + 1, s + 1, shB, shA, soB, soA, ig, xl);
        }
    }
    // last step (odd) wrote soB
    if (tid == 256) {
        float4 a = *(const float4*)soB;
        float4 b4 = *(const float4*)(soB + 4);
        out[TT - 1] = a.x + a.y + a.z + a.w + b4.x + b4.y + b4.z + b4.w + lbias;
    }
}

extern "C" void kernel_launch(void* const* d_in, const int* in_sizes, int n_in,
                              void* d_out, int out_size) {
    const float* x_gru = (const float*)d_in[0];  // (65536, 96)
    const float* x_lin = (const float*)d_in[1];  // (65536, 32)
    const float* h0    = (const float*)d_in[2];  // (128,)
    const float* w_ih  = (const float*)d_in[3];  // (384, 96)
    const float* w_hh  = (const float*)d_in[4];  // (384, 128)
    const float* b_ih  = (const float*)d_in[5];  // (384,)
    const float* b_n   = (const float*)d_in[6];  // (128,)
    const float* lb    = (const float*)d_in[7];  // (1,)
    float* out = (float*)d_out;                  // (65536, 1)

    gru_clear_flags<<<(NCHUNK + 255) / 256, 256>>>();
    gru_fused<<<NBLK, NT>>>(x_gru, x_lin, h0, w_ih, w_hh, b_ih, b_n, lb, out);
}